// round 13
// baseline (speedup 1.0000x reference)
#include <cuda_runtime.h>
#include <cstdint>

// Problem constants (fixed shapes per reference)
constexpr int  VOCAB   = 32000;
constexpr int  HIDDEN  = 2048;
constexpr int  EMB_DIM = 512;
constexpr long long HASH_BASE = 128000;
constexpr int  SEQ  = 2048;
constexpr int  MTOT = 8192;          // B*S
constexpr int  EOS_TOK = 2;

constexpr int BM = 128, BN = 128, BK = 32;
constexpr int TILEF = BM * BK;       // 4096 floats per tile
constexpr int SMEM_BYTES = 2 * 2 * TILEF * 4;  // 2 bufs * (A+B) = 64 KB

// scratch: hashed ngram ids per table + dtype-normalized token ids
__device__ int g_newids[4][MTOT];
__device__ int g_ids32[MTOT];

// input_ids arrives either as int32 (harness downcast) or true int64.
// Probe odd 32-bit words of the first 16 elements: all-zero <=> int64 layout
// (tokens < 2^15; P[16 random int32 tokens all zero] ~ 32000^-16).
__global__ void newids_kernel(const unsigned* __restrict__ raw) {
    bool is64 = true;
#pragma unroll
    for (int i = 1; i < 32; i += 2) is64 &= (raw[i] == 0u);

    const long long* as64 = (const long long*)raw;
    const int*       as32 = (const int*)raw;

    int t = blockIdx.x * blockDim.x + threadIdx.x;
    if (t >= MTOT) return;
    int s = t & (SEQ - 1);

    int id0 = is64 ? (int)as64[t] : as32[t];
    int p1v = (s >= 1) ? (is64 ? (int)as64[t - 1] : as32[t - 1]) : EOS_TOK;
    int p2v = (s >= 2) ? (is64 ? (int)as64[t - 2] : as32[t - 2]) : EOS_TOK;

    g_ids32[t] = id0;

    long long sh2 = (s >= 1 && p1v != EOS_TOK) ? p1v : 0;                      // shift-1, EOS-segmented
    long long sh3 = (s >= 2 && p1v != EOS_TOK && p2v != EOS_TOK) ? p2v : 0;    // shift-2, EOS-segmented
#pragma unroll
    for (int e = 0; e < 4; e++) {
        long long dim = HASH_BASE + 2 * e + 1;
        long long m1 = ((long long)VOCAB) % dim;
        long long ng;
        if (e < 2) {
            ng = (long long)id0 + sh2 * m1;              // bigram tables 0,1
        } else {
            long long m2 = (m1 * (long long)VOCAB) % dim;
            ng = (long long)id0 + sh2 * m1 + sh3 * m2;   // trigram tables 2,3
        }
        g_newids[e][t] = (int)(ng % dim);
    }
}

__device__ __forceinline__ float to_tf32(float x) {
    unsigned u;
    asm("cvt.rna.tf32.f32 %0, %1;" : "=r"(u) : "f"(x));
    return __uint_as_float(u);
}

__global__ void __launch_bounds__(256, 1)
ngram_gemm_kernel(const float* __restrict__ wemb,
                  const float* __restrict__ e0, const float* __restrict__ e1,
                  const float* __restrict__ e2, const float* __restrict__ e3,
                  const float* __restrict__ p0, const float* __restrict__ p1,
                  const float* __restrict__ p2, const float* __restrict__ p3,
                  float* __restrict__ out)
{
    extern __shared__ float smem[];
    const int tid  = threadIdx.x;
    const int lane = tid & 31, warp = tid >> 5;
    const int wm = warp >> 2, wn = warp & 3;          // 2 x 4 warp grid (64x32 tiles)
    const int g = lane >> 2, c = lane & 3;
    const int bm = blockIdx.y * BM, bn = blockIdx.x * BN;

    // staging assignment: 128 rows x 8 float4-cols, 4 passes of 32 rows
    const int srow = tid >> 3;   // 0..31
    const int sc4  = tid & 7;    // 0..7

    float acc[4][4][4];
#pragma unroll
    for (int mf = 0; mf < 4; mf++)
#pragma unroll
        for (int nf = 0; nf < 4; nf++)
#pragma unroll
            for (int r = 0; r < 4; r++) acc[mf][nf][r] = 0.f;

    float4 areg[4], breg[4];

    auto load_tiles = [&](int it) {
        const int e    = it >> 4;            // table index (512/32 = 16 iters per table)
        const int koff = (it << 5) & 511;    // offset within the 512-dim table row
        const float* eb = (e == 0) ? e0 : (e == 1) ? e1 : (e == 2) ? e2 : e3;
        const float* pb = (e == 0) ? p0 : (e == 1) ? p1 : (e == 2) ? p2 : p3;
#pragma unroll
        for (int p = 0; p < 4; p++) {
            int row = p * 32 + srow;
            int nv  = g_newids[e][bm + row];
            areg[p] = *reinterpret_cast<const float4*>(eb + (size_t)nv * EMB_DIM + koff + sc4 * 4);
            breg[p] = *reinterpret_cast<const float4*>(pb + (size_t)(bn + row) * EMB_DIM + koff + sc4 * 4);
        }
    };

    auto store_tiles = [&](int buf) {
        float* As = smem + buf * 2 * TILEF;
        float* Bs = As + TILEF;
#pragma unroll
        for (int p = 0; p < 4; p++) {
            int row = p * 32 + srow;
            int ko  = (sc4 * 4) ^ ((row & 7) << 2);   // XOR swizzle, keeps float4 contiguous
            float4 a = areg[p];
            float4 b = breg[p];
            float4 ta = make_float4(to_tf32(a.x), to_tf32(a.y), to_tf32(a.z), to_tf32(a.w));
            float4 tb = make_float4(to_tf32(b.x), to_tf32(b.y), to_tf32(b.z), to_tf32(b.w));
            *reinterpret_cast<float4*>(As + row * 32 + ko) = ta;
            *reinterpret_cast<float4*>(Bs + row * 32 + ko) = tb;
        }
    };

    auto compute = [&](int buf) {
        const float* As = smem + buf * 2 * TILEF;
        const float* Bs = As + TILEF;
        const int sw = g << 2;
#pragma unroll
        for (int ks = 0; ks < 4; ks++) {
            const int kk = ks * 8;
            const int ka = (kk + c) ^ sw;
            const int kb = (kk + c + 4) ^ sw;
            unsigned av[4][4];
            unsigned bv[4][2];
#pragma unroll
            for (int mf = 0; mf < 4; mf++) {
                const float* base = As + (wm * 64 + mf * 16 + g) * 32;
                av[mf][0] = __float_as_uint(base[ka]);
                av[mf][1] = __float_as_uint(base[8 * 32 + ka]);
                av[mf][2] = __float_as_uint(base[kb]);
                av[mf][3] = __float_as_uint(base[8 * 32 + kb]);
            }
#pragma unroll
            for (int nf = 0; nf < 4; nf++) {
                const float* base = Bs + (wn * 32 + nf * 8 + g) * 32;
                bv[nf][0] = __float_as_uint(base[ka]);
                bv[nf][1] = __float_as_uint(base[kb]);
            }
#pragma unroll
            for (int mf = 0; mf < 4; mf++)
#pragma unroll
                for (int nf = 0; nf < 4; nf++) {
                    asm("mma.sync.aligned.m16n8k8.row.col.f32.tf32.tf32.f32 "
                        "{%0,%1,%2,%3}, {%4,%5,%6,%7}, {%8,%9}, {%0,%1,%2,%3};"
                        : "+f"(acc[mf][nf][0]), "+f"(acc[mf][nf][1]),
                          "+f"(acc[mf][nf][2]), "+f"(acc[mf][nf][3])
                        : "r"(av[mf][0]), "r"(av[mf][1]), "r"(av[mf][2]), "r"(av[mf][3]),
                          "r"(bv[nf][0]), "r"(bv[nf][1]));
                }
        }
    };

    // double-buffered mainloop over K = 2048 (64 iters of BK=32)
    load_tiles(0);
    store_tiles(0);
    __syncthreads();
    for (int it = 0; it < 64; it++) {
        const int buf = it & 1;
        if (it + 1 < 64) load_tiles(it + 1);
        compute(buf);
        if (it + 1 < 64) {
            store_tiles(buf ^ 1);
            __syncthreads();
        }
    }

    // epilogue: fuse word_emb gather + /5  (token ids via normalized g_ids32)
    const float inv = 0.2f;
#pragma unroll
    for (int mf = 0; mf < 4; mf++) {
        int r0 = bm + wm * 64 + mf * 16 + g;
        int r1 = r0 + 8;
        int i0 = g_ids32[r0], i1 = g_ids32[r1];
        const float* w0 = wemb + (size_t)i0 * HIDDEN;
        const float* w1 = wemb + (size_t)i1 * HIDDEN;
        float* o0 = out + (size_t)r0 * HIDDEN;
        float* o1 = out + (size_t)r1 * HIDDEN;
#pragma unroll
        for (int nf = 0; nf < 4; nf++) {
            int col = bn + wn * 32 + nf * 8 + 2 * c;
            float2 wa = *reinterpret_cast<const float2*>(w0 + col);
            float2 wb = *reinterpret_cast<const float2*>(w1 + col);
            float2 oa, ob;
            oa.x = (wa.x + acc[mf][nf][0]) * inv;
            oa.y = (wa.y + acc[mf][nf][1]) * inv;
            ob.x = (wb.x + acc[mf][nf][2]) * inv;
            ob.y = (wb.y + acc[mf][nf][3]) * inv;
            *reinterpret_cast<float2*>(o0 + col) = oa;
            *reinterpret_cast<float2*>(o1 + col) = ob;
        }
    }
}

extern "C" void kernel_launch(void* const* d_in, const int* in_sizes, int n_in,
                              void* d_out, int out_size)
{
    const unsigned* ids_raw = (const unsigned*)d_in[0];
    const float*    wemb    = (const float*)d_in[1];
    float* out = (float*)d_out;

    // Bind emb/proj pointers by SIZE, not by assumed metadata order.
    // emb_i has (128001 + 2i) * 512 elements (unique per i, > 2M);
    // every proj has 2048 * 512 = 1,048,576 elements. In both plausible
    // orderings (interleaved emb0,proj0,... or grouped emb0..emb3,proj0..proj3)
    // the projs appear in index order, so k-th proj encountered == proj_k.
    const float* embs[4]  = {nullptr, nullptr, nullptr, nullptr};
    const float* projs[4] = {nullptr, nullptr, nullptr, nullptr};
    int np = 0;
    for (int i = 2; i < n_in && i < 10; i++) {
        long long sz = in_sizes[i];
        if (sz == (long long)HIDDEN * EMB_DIM) {          // 1,048,576 -> proj
            if (np < 4) projs[np++] = (const float*)d_in[i];
        } else {                                           // emb table
            int dim = (int)(sz / EMB_DIM);
            int idx = (dim - ((int)HASH_BASE + 1)) / 2;
            if (idx >= 0 && idx < 4) embs[idx] = (const float*)d_in[i];
        }
    }

    newids_kernel<<<MTOT / 256, 256>>>(ids_raw);

    cudaFuncSetAttribute(ngram_gemm_kernel,
                         cudaFuncAttributeMaxDynamicSharedMemorySize, SMEM_BYTES);
    dim3 grid(HIDDEN / BN, MTOT / BM);  // (16, 64): x-fastest -> same-A CTAs co-resident for L2 reuse
    ngram_gemm_kernel<<<grid, 256, SMEM_BYTES>>>(wemb,
                                                 embs[0], embs[1], embs[2], embs[3],
                                                 projs[0], projs[1], projs[2], projs[3],
                                                 out);
}

// round 14
// speedup vs baseline: 1.5426x; 1.5426x over previous
#include <cuda_runtime.h>
#include <cstdint>

// Problem constants (fixed shapes per reference)
constexpr int  VOCAB   = 32000;
constexpr int  HIDDEN  = 2048;
constexpr int  EMB_DIM = 512;
constexpr long long HASH_BASE = 128000;
constexpr int  SEQ  = 2048;
constexpr int  MTOT = 8192;          // B*S
constexpr int  EOS_TOK = 2;

constexpr int BM = 128, BN = 128, BK = 32;
constexpr int STAGES = 3;
constexpr int TILEF = BM * BK;                      // 4096 floats per tile
constexpr int SMEM_BYTES = STAGES * 2 * TILEF * 4;  // 3 stages * (A+B) = 96 KB

// scratch
__device__ int   g_newids[4][MTOT];
__device__ int   g_ids32[MTOT];
__device__ float g_A[(size_t)MTOT * HIDDEN];    // gathered + tf32-rounded A (64 MB)
__device__ float g_B[(size_t)HIDDEN * HIDDEN];  // packed  + tf32-rounded B (16 MB)

__device__ __forceinline__ float to_tf32(float x) {
    unsigned u;
    asm("cvt.rna.tf32.f32 %0, %1;" : "=r"(u) : "f"(x));
    return __uint_as_float(u);
}
__device__ __forceinline__ float4 cvt4(float4 v) {
    return make_float4(to_tf32(v.x), to_tf32(v.y), to_tf32(v.z), to_tf32(v.w));
}

// input_ids arrives either as int32 (harness downcast) or true int64.
// Probe odd 32-bit words of the first 16 elements: all-zero <=> int64 layout.
__global__ void newids_kernel(const unsigned* __restrict__ raw) {
    bool is64 = true;
#pragma unroll
    for (int i = 1; i < 32; i += 2) is64 &= (raw[i] == 0u);

    const long long* as64 = (const long long*)raw;
    const int*       as32 = (const int*)raw;

    int t = blockIdx.x * blockDim.x + threadIdx.x;
    if (t >= MTOT) return;
    int s = t & (SEQ - 1);

    int id0 = is64 ? (int)as64[t] : as32[t];
    int p1v = (s >= 1) ? (is64 ? (int)as64[t - 1] : as32[t - 1]) : EOS_TOK;
    int p2v = (s >= 2) ? (is64 ? (int)as64[t - 2] : as32[t - 2]) : EOS_TOK;

    g_ids32[t] = id0;

    long long sh2 = (s >= 1 && p1v != EOS_TOK) ? p1v : 0;                      // shift-1, EOS-segmented
    long long sh3 = (s >= 2 && p1v != EOS_TOK && p2v != EOS_TOK) ? p2v : 0;    // shift-2, EOS-segmented
#pragma unroll
    for (int e = 0; e < 4; e++) {
        long long dim = HASH_BASE + 2 * e + 1;
        long long m1 = ((long long)VOCAB) % dim;
        long long ng;
        if (e < 2) {
            ng = (long long)id0 + sh2 * m1;              // bigram tables 0,1
        } else {
            long long m2 = (m1 * (long long)VOCAB) % dim;
            ng = (long long)id0 + sh2 * m1 + sh3 * m2;   // trigram tables 2,3
        }
        g_newids[e][t] = (int)(ng % dim);
    }
}

// Gather A rows (emb tables via hashed ids) and pack B rows (projs), both
// pre-rounded to tf32 so the GEMM mainloop is a pure dense copy+mma.
__global__ void pack_kernel(const float* __restrict__ e0, const float* __restrict__ e1,
                            const float* __restrict__ e2, const float* __restrict__ e3,
                            const float* __restrict__ p0, const float* __restrict__ p1,
                            const float* __restrict__ p2, const float* __restrict__ p3)
{
    int b = blockIdx.x;
    if (b < MTOT) {
        int t = b;
#pragma unroll
        for (int r = 0; r < 2; r++) {
            int i = threadIdx.x + r * 256;        // float4 index 0..511
            int e = i >> 7;
            int koff = (i & 127) * 4;
            const float* eb = (e == 0) ? e0 : (e == 1) ? e1 : (e == 2) ? e2 : e3;
            int nv = g_newids[e][t];
            float4 v = *reinterpret_cast<const float4*>(eb + (size_t)nv * EMB_DIM + koff);
            *reinterpret_cast<float4*>(g_A + (size_t)t * HIDDEN + e * EMB_DIM + koff) = cvt4(v);
        }
    } else {
        int n = b - MTOT;                         // 0..2047
#pragma unroll
        for (int r = 0; r < 2; r++) {
            int i = threadIdx.x + r * 256;
            int e = i >> 7;
            int koff = (i & 127) * 4;
            const float* pb = (e == 0) ? p0 : (e == 1) ? p1 : (e == 2) ? p2 : p3;
            float4 v = *reinterpret_cast<const float4*>(pb + (size_t)n * EMB_DIM + koff);
            *reinterpret_cast<float4*>(g_B + (size_t)n * HIDDEN + e * EMB_DIM + koff) = cvt4(v);
        }
    }
}

__device__ __forceinline__ void cp_async16(unsigned dst, const float* src) {
    asm volatile("cp.async.cg.shared.global [%0], [%1], 16;" :: "r"(dst), "l"(src));
}

__global__ void __launch_bounds__(256, 2)
ngram_gemm_kernel(const float* __restrict__ wemb, float* __restrict__ out)
{
    extern __shared__ float smem[];
    const unsigned smem_u = (unsigned)__cvta_generic_to_shared(smem);
    const int tid  = threadIdx.x;
    const int lane = tid & 31, warp = tid >> 5;
    const int wm = warp >> 2, wn = warp & 3;          // 2 x 4 warp grid (64x32 tiles)
    const int g = lane >> 2, c = lane & 3;
    const int bm = blockIdx.y * BM, bn = blockIdx.x * BN;

    // staging: 128 rows x 8 float4-cols, 4 passes of 32 rows
    const int srow = tid >> 3;   // 0..31
    const int sc4  = tid & 7;    // 0..7
    const int scol = sc4 * 4;

    float acc[4][4][4];
#pragma unroll
    for (int mf = 0; mf < 4; mf++)
#pragma unroll
        for (int nf = 0; nf < 4; nf++)
#pragma unroll
            for (int r = 0; r < 4; r++) acc[mf][nf][r] = 0.f;

    const float* Agb = g_A + (size_t)bm * HIDDEN;
    const float* Bgb = g_B + (size_t)bn * HIDDEN;

    auto issue = [&](int it, int buf) {
        const unsigned sb = smem_u + (unsigned)buf * 2 * TILEF * 4;
        const float* Ag = Agb + it * BK;
        const float* Bg = Bgb + it * BK;
#pragma unroll
        for (int p = 0; p < 4; p++) {
            int row = p * 32 + srow;
            int ko  = scol ^ ((row & 7) << 2);   // XOR swizzle, float4-contiguous
            cp_async16(sb + (row * 32 + ko) * 4,             Ag + (size_t)row * HIDDEN + scol);
            cp_async16(sb + (TILEF + row * 32 + ko) * 4,     Bg + (size_t)row * HIDDEN + scol);
        }
    };

    auto compute = [&](int buf) {
        const float* As = smem + buf * 2 * TILEF;
        const float* Bs = As + TILEF;
        const int sw = g << 2;
#pragma unroll
        for (int ks = 0; ks < 4; ks++) {
            const int kk = ks * 8;
            const int ka = (kk + c) ^ sw;
            const int kb = (kk + c + 4) ^ sw;
            unsigned av[4][4];
            unsigned bv[4][2];
#pragma unroll
            for (int mf = 0; mf < 4; mf++) {
                const float* base = As + (wm * 64 + mf * 16 + g) * 32;
                av[mf][0] = __float_as_uint(base[ka]);
                av[mf][1] = __float_as_uint(base[8 * 32 + ka]);
                av[mf][2] = __float_as_uint(base[kb]);
                av[mf][3] = __float_as_uint(base[8 * 32 + kb]);
            }
#pragma unroll
            for (int nf = 0; nf < 4; nf++) {
                const float* base = Bs + (wn * 32 + nf * 8 + g) * 32;
                bv[nf][0] = __float_as_uint(base[ka]);
                bv[nf][1] = __float_as_uint(base[kb]);
            }
#pragma unroll
            for (int mf = 0; mf < 4; mf++)
#pragma unroll
                for (int nf = 0; nf < 4; nf++) {
                    asm("mma.sync.aligned.m16n8k8.row.col.f32.tf32.tf32.f32 "
                        "{%0,%1,%2,%3}, {%4,%5,%6,%7}, {%8,%9}, {%0,%1,%2,%3};"
                        : "+f"(acc[mf][nf][0]), "+f"(acc[mf][nf][1]),
                          "+f"(acc[mf][nf][2]), "+f"(acc[mf][nf][3])
                        : "r"(av[mf][0]), "r"(av[mf][1]), "r"(av[mf][2]), "r"(av[mf][3]),
                          "r"(bv[nf][0]), "r"(bv[nf][1]));
                }
        }
    };

    // 3-stage cp.async pipeline over K = 2048 (64 iters of BK=32)
    issue(0, 0); asm volatile("cp.async.commit_group;");
    issue(1, 1); asm volatile("cp.async.commit_group;");
    issue(2, 2); asm volatile("cp.async.commit_group;");

    for (int it = 0; it < 64; it++) {
        asm volatile("cp.async.wait_group 2;");
        __syncthreads();                      // stage 'it' visible to all warps
        const int buf = it % 3;
        compute(buf);
        __syncthreads();                      // all warps done reading buf
        if (it + 3 < 64) issue(it + 3, buf);
        asm volatile("cp.async.commit_group;");  // empty groups at tail keep wait_group uniform
    }

    // epilogue: fuse word_emb gather + /5
    const float inv = 0.2f;
#pragma unroll
    for (int mf = 0; mf < 4; mf++) {
        int r0 = bm + wm * 64 + mf * 16 + g;
        int r1 = r0 + 8;
        int i0 = g_ids32[r0], i1 = g_ids32[r1];
        const float* w0 = wemb + (size_t)i0 * HIDDEN;
        const float* w1 = wemb + (size_t)i1 * HIDDEN;
        float* o0 = out + (size_t)r0 * HIDDEN;
        float* o1 = out + (size_t)r1 * HIDDEN;
#pragma unroll
        for (int nf = 0; nf < 4; nf++) {
            int col = bn + wn * 32 + nf * 8 + 2 * c;
            float2 wa = *reinterpret_cast<const float2*>(w0 + col);
            float2 wb = *reinterpret_cast<const float2*>(w1 + col);
            float2 oa, ob;
            oa.x = (wa.x + acc[mf][nf][0]) * inv;
            oa.y = (wa.y + acc[mf][nf][1]) * inv;
            ob.x = (wb.x + acc[mf][nf][2]) * inv;
            ob.y = (wb.y + acc[mf][nf][3]) * inv;
            *reinterpret_cast<float2*>(o0 + col) = oa;
            *reinterpret_cast<float2*>(o1 + col) = ob;
        }
    }
}

extern "C" void kernel_launch(void* const* d_in, const int* in_sizes, int n_in,
                              void* d_out, int out_size)
{
    const unsigned* ids_raw = (const unsigned*)d_in[0];
    const float*    wemb    = (const float*)d_in[1];
    float* out = (float*)d_out;

    // Bind emb/proj pointers by SIZE (robust to metadata ordering).
    const float* embs[4]  = {nullptr, nullptr, nullptr, nullptr};
    const float* projs[4] = {nullptr, nullptr, nullptr, nullptr};
    int np = 0;
    for (int i = 2; i < n_in && i < 10; i++) {
        long long sz = in_sizes[i];
        if (sz == (long long)HIDDEN * EMB_DIM) {          // 1,048,576 -> proj
            if (np < 4) projs[np++] = (const float*)d_in[i];
        } else {                                           // emb table: unique size per idx
            int dim = (int)(sz / EMB_DIM);
            int idx = (dim - ((int)HASH_BASE + 1)) / 2;
            if (idx >= 0 && idx < 4) embs[idx] = (const float*)d_in[i];
        }
    }

    newids_kernel<<<MTOT / 256, 256>>>(ids_raw);
    pack_kernel<<<MTOT + HIDDEN, 256>>>(embs[0], embs[1], embs[2], embs[3],
                                        projs[0], projs[1], projs[2], projs[3]);

    cudaFuncSetAttribute(ngram_gemm_kernel,
                         cudaFuncAttributeMaxDynamicSharedMemorySize, SMEM_BYTES);
    dim3 grid(HIDDEN / BN, MTOT / BM);  // (16, 64)
    ngram_gemm_kernel<<<grid, 256, SMEM_BYTES>>>(wemb, out);
}

// round 16
// speedup vs baseline: 1.8396x; 1.1925x over previous
#include <cuda_runtime.h>
#include <cuda_fp16.h>
#include <cstdint>

// Problem constants (fixed shapes per reference)
constexpr int  VOCAB   = 32000;
constexpr int  HIDDEN  = 2048;
constexpr int  EMB_DIM = 512;
constexpr long long HASH_BASE = 128000;
constexpr int  SEQ  = 2048;
constexpr int  MTOT = 8192;          // B*S
constexpr int  EOS_TOK = 2;

// GEMM tiling (mma.sync m16n8k16 fp16, fp32 accum)
constexpr int BM = 128, BN = 128, BK = 32;
constexpr int STAGES = 3;
constexpr int ROW_BYTES = 80;                        // 64B data + 16B pad (16B-aligned, conflict-free)
constexpr int ROW_U32   = ROW_BYTES / 4;             // 20
constexpr int TILE_BYTES  = BM * ROW_BYTES;          // 10240
constexpr int STAGE_BYTES = 2 * TILE_BYTES;          // A+B = 20480
constexpr int SMEM_BYTES  = STAGES * STAGE_BYTES;    // 60 KB

// scratch
__device__ int    g_newids[4][MTOT];
__device__ int    g_ids32[MTOT];
__device__ __half g_A[(size_t)MTOT * HIDDEN];    // gathered A, fp16 (32 MB)
__device__ __half g_B[(size_t)HIDDEN * HIDDEN];  // packed  B, fp16 (8 MB)

// input_ids arrives either as int32 (harness downcast) or true int64.
// Probe odd 32-bit words of the first 16 elements: all-zero <=> int64 layout.
__global__ void newids_kernel(const unsigned* __restrict__ raw) {
    bool is64 = true;
#pragma unroll
    for (int i = 1; i < 32; i += 2) is64 &= (raw[i] == 0u);

    const long long* as64 = (const long long*)raw;
    const int*       as32 = (const int*)raw;

    int t = blockIdx.x * blockDim.x + threadIdx.x;
    if (t >= MTOT) return;
    int s = t & (SEQ - 1);

    int id0 = is64 ? (int)as64[t] : as32[t];
    int p1v = (s >= 1) ? (is64 ? (int)as64[t - 1] : as32[t - 1]) : EOS_TOK;
    int p2v = (s >= 2) ? (is64 ? (int)as64[t - 2] : as32[t - 2]) : EOS_TOK;

    g_ids32[t] = id0;

    long long sh2 = (s >= 1 && p1v != EOS_TOK) ? p1v : 0;                      // shift-1, EOS-segmented
    long long sh3 = (s >= 2 && p1v != EOS_TOK && p2v != EOS_TOK) ? p2v : 0;    // shift-2, EOS-segmented
#pragma unroll
    for (int e = 0; e < 4; e++) {
        long long dim = HASH_BASE + 2 * e + 1;
        long long m1 = ((long long)VOCAB) % dim;
        long long ng;
        if (e < 2) {
            ng = (long long)id0 + sh2 * m1;              // bigram tables 0,1
        } else {
            long long m2 = (m1 * (long long)VOCAB) % dim;
            ng = (long long)id0 + sh2 * m1 + sh3 * m2;   // trigram tables 2,3
        }
        g_newids[e][t] = (int)(ng % dim);
    }
}

// Gather A rows (emb tables via hashed ids) and pack B rows (projs) to fp16.
__global__ void pack_kernel(const float* __restrict__ e0, const float* __restrict__ e1,
                            const float* __restrict__ e2, const float* __restrict__ e3,
                            const float* __restrict__ p0, const float* __restrict__ p1,
                            const float* __restrict__ p2, const float* __restrict__ p3)
{
    int b = blockIdx.x;
    if (b < MTOT) {
        int t = b;
#pragma unroll
        for (int r = 0; r < 2; r++) {
            int i = threadIdx.x + r * 256;        // float4 index 0..511
            int e = i >> 7;
            int koff = (i & 127) * 4;
            const float* eb = (e == 0) ? e0 : (e == 1) ? e1 : (e == 2) ? e2 : e3;
            int nv = g_newids[e][t];
            float4 v = *reinterpret_cast<const float4*>(eb + (size_t)nv * EMB_DIM + koff);
            __half2 h0 = __floats2half2_rn(v.x, v.y);
            __half2 h1 = __floats2half2_rn(v.z, v.w);
            *reinterpret_cast<__half2*>(g_A + (size_t)t * HIDDEN + e * EMB_DIM + koff)     = h0;
            *reinterpret_cast<__half2*>(g_A + (size_t)t * HIDDEN + e * EMB_DIM + koff + 2) = h1;
        }
    } else {
        int n = b - MTOT;                         // 0..2047
#pragma unroll
        for (int r = 0; r < 2; r++) {
            int i = threadIdx.x + r * 256;
            int e = i >> 7;
            int koff = (i & 127) * 4;
            const float* pb = (e == 0) ? p0 : (e == 1) ? p1 : (e == 2) ? p2 : p3;
            float4 v = *reinterpret_cast<const float4*>(pb + (size_t)n * EMB_DIM + koff);
            __half2 h0 = __floats2half2_rn(v.x, v.y);
            __half2 h1 = __floats2half2_rn(v.z, v.w);
            *reinterpret_cast<__half2*>(g_B + (size_t)n * HIDDEN + e * EMB_DIM + koff)     = h0;
            *reinterpret_cast<__half2*>(g_B + (size_t)n * HIDDEN + e * EMB_DIM + koff + 2) = h1;
        }
    }
}

__device__ __forceinline__ void cp_async16(unsigned dst, const void* src) {
    asm volatile("cp.async.cg.shared.global [%0], [%1], 16;" :: "r"(dst), "l"(src));
}

__global__ void __launch_bounds__(256, 2)
ngram_gemm_kernel(const float* __restrict__ wemb, float* __restrict__ out)
{
    extern __shared__ char smem[];
    const unsigned smem_u = (unsigned)__cvta_generic_to_shared(smem);
    const int tid  = threadIdx.x;
    const int lane = tid & 31, warp = tid >> 5;
    const int wm = warp >> 2, wn = warp & 3;          // 2 x 4 warp grid (64x32 tiles)
    const int g = lane >> 2, c = lane & 3;
    const int bm = blockIdx.y * BM, bn = blockIdx.x * BN;

    // staging: 512 16B-chunks per tile (128 rows x 4 chunks), 2 per thread
    const int crow = tid >> 1;          // 0..127
    const int cgrp2 = (tid & 1) * 2;    // chunks {0,1} or {2,3}

    float acc[4][4][4];
#pragma unroll
    for (int mf = 0; mf < 4; mf++)
#pragma unroll
        for (int nf = 0; nf < 4; nf++)
#pragma unroll
            for (int r = 0; r < 4; r++) acc[mf][nf][r] = 0.f;

    const __half* Agb = g_A + (size_t)bm * HIDDEN;
    const __half* Bgb = g_B + (size_t)bn * HIDDEN;

    auto issue = [&](int it, int buf) {
        const unsigned sa = smem_u + (unsigned)buf * STAGE_BYTES;
        const unsigned sb = sa + TILE_BYTES;
        const __half* Ag = Agb + it * BK;
        const __half* Bg = Bgb + it * BK;
#pragma unroll
        for (int q = 0; q < 2; q++) {
            int grp = cgrp2 + q;
            cp_async16(sa + crow * ROW_BYTES + grp * 16, Ag + (size_t)crow * HIDDEN + grp * 8);
            cp_async16(sb + crow * ROW_BYTES + grp * 16, Bg + (size_t)crow * HIDDEN + grp * 8);
        }
        asm volatile("cp.async.commit_group;" ::: "memory");
    };

    auto compute = [&](int buf) {
        const unsigned* As = (const unsigned*)(smem + buf * STAGE_BYTES);
        const unsigned* Bs = As + TILE_BYTES / 4;
#pragma unroll
        for (int ks = 0; ks < 2; ks++) {           // two k16 steps cover BK=32
            const int pa0 = ks * 8 + c;            // fp16-pair index (k = 2*pa)
            const int pa1 = pa0 + 4;
            unsigned av[4][4], bv[4][2];
#pragma unroll
            for (int mf = 0; mf < 4; mf++) {
                const int r0 = wm * 64 + mf * 16 + g;
                av[mf][0] = As[r0 * ROW_U32 + pa0];
                av[mf][1] = As[(r0 + 8) * ROW_U32 + pa0];
                av[mf][2] = As[r0 * ROW_U32 + pa1];
                av[mf][3] = As[(r0 + 8) * ROW_U32 + pa1];
            }
#pragma unroll
            for (int nf = 0; nf < 4; nf++) {
                const int rb = wn * 32 + nf * 8 + g;
                bv[nf][0] = Bs[rb * ROW_U32 + pa0];
                bv[nf][1] = Bs[rb * ROW_U32 + pa1];
            }
#pragma unroll
            for (int mf = 0; mf < 4; mf++)
#pragma unroll
                for (int nf = 0; nf < 4; nf++) {
                    asm("mma.sync.aligned.m16n8k16.row.col.f32.f16.f16.f32 "
                        "{%0,%1,%2,%3}, {%4,%5,%6,%7}, {%8,%9}, {%0,%1,%2,%3};"
                        : "+f"(acc[mf][nf][0]), "+f"(acc[mf][nf][1]),
                          "+f"(acc[mf][nf][2]), "+f"(acc[mf][nf][3])
                        : "r"(av[mf][0]), "r"(av[mf][1]), "r"(av[mf][2]), "r"(av[mf][3]),
                          "r"(bv[nf][0]), "r"(bv[nf][1]));
                }
        }
    };

    // 3-stage cp.async pipeline over K = 2048 (64 iters of BK=32)
    issue(0, 0); issue(1, 1); issue(2, 2);

    for (int it = 0; it < 64; it++) {
        asm volatile("cp.async.wait_group 2;" ::: "memory");
        __syncthreads();                      // stage 'it' visible to all warps
        const int buf = it % 3;
        compute(buf);
        __syncthreads();                      // all warps done reading buf
        if (it + 3 < 64) issue(it + 3, buf);
        else asm volatile("cp.async.commit_group;" ::: "memory");  // keep group count uniform
    }

    // epilogue: fuse word_emb gather + /5 (fp32 accumulators)
    const float inv = 0.2f;
#pragma unroll
    for (int mf = 0; mf < 4; mf++) {
        int r0 = bm + wm * 64 + mf * 16 + g;
        int r1 = r0 + 8;
        int i0 = g_ids32[r0], i1 = g_ids32[r1];
        const float* w0 = wemb + (size_t)i0 * HIDDEN;
        const float* w1 = wemb + (size_t)i1 * HIDDEN;
        float* o0 = out + (size_t)r0 * HIDDEN;
        float* o1 = out + (size_t)r1 * HIDDEN;
#pragma unroll
        for (int nf = 0; nf < 4; nf++) {
            int col = bn + wn * 32 + nf * 8 + 2 * c;
            float2 wa = *reinterpret_cast<const float2*>(w0 + col);
            float2 wb = *reinterpret_cast<const float2*>(w1 + col);
            float2 oa, ob;
            oa.x = (wa.x + acc[mf][nf][0]) * inv;
            oa.y = (wa.y + acc[mf][nf][1]) * inv;
            ob.x = (wb.x + acc[mf][nf][2]) * inv;
            ob.y = (wb.y + acc[mf][nf][3]) * inv;
            *reinterpret_cast<float2*>(o0 + col) = oa;
            *reinterpret_cast<float2*>(o1 + col) = ob;
        }
    }
}

extern "C" void kernel_launch(void* const* d_in, const int* in_sizes, int n_in,
                              void* d_out, int out_size)
{
    const unsigned* ids_raw = (const unsigned*)d_in[0];
    const float*    wemb    = (const float*)d_in[1];
    float* out = (float*)d_out;

    // Bind emb/proj pointers by SIZE (robust to metadata ordering).
    const float* embs[4]  = {nullptr, nullptr, nullptr, nullptr};
    const float* projs[4] = {nullptr, nullptr, nullptr, nullptr};
    int np = 0;
    for (int i = 2; i < n_in && i < 10; i++) {
        long long sz = in_sizes[i];
        if (sz == (long long)HIDDEN * EMB_DIM) {          // 1,048,576 -> proj
            if (np < 4) projs[np++] = (const float*)d_in[i];
        } else {                                           // emb table: unique size per idx
            int dim = (int)(sz / EMB_DIM);
            int idx = (dim - ((int)HASH_BASE + 1)) / 2;
            if (idx >= 0 && idx < 4) embs[idx] = (const float*)d_in[i];
        }
    }

    newids_kernel<<<MTOT / 256, 256>>>(ids_raw);
    pack_kernel<<<MTOT + HIDDEN, 256>>>(embs[0], embs[1], embs[2], embs[3],
                                        projs[0], projs[1], projs[2], projs[3]);

    cudaFuncSetAttribute(ngram_gemm_kernel,
                         cudaFuncAttributeMaxDynamicSharedMemorySize, SMEM_BYTES);
    dim3 grid(HIDDEN / BN, MTOT / BM);  // (16, 64)
    ngram_gemm_kernel<<<grid, 256, SMEM_BYTES>>>(wemb, out);
}

// round 17
// speedup vs baseline: 2.0847x; 1.1332x over previous
#include <cuda_runtime.h>
#include <cuda_fp16.h>
#include <cstdint>

// Problem constants (fixed shapes per reference)
constexpr int  VOCAB   = 32000;
constexpr int  HIDDEN  = 2048;
constexpr int  EMB_DIM = 512;
constexpr long long HASH_BASE = 128000;
constexpr int  SEQ  = 2048;
constexpr int  MTOT = 8192;          // B*S
constexpr int  EOS_TOK = 2;

// GEMM tiling (mma.sync m16n8k16 fp16, fp32 accum)
constexpr int BM = 128, BN = 128, BK = 32;
constexpr int STAGES = 4;
constexpr int ROW_BYTES = 80;                        // 64B data + 16B pad (conflict-free, LDSM-safe)
constexpr int TILE_BYTES  = BM * ROW_BYTES;          // 10240
constexpr int STAGE_BYTES = 2 * TILE_BYTES;          // A+B = 20480
constexpr int SMEM_BYTES  = STAGES * STAGE_BYTES;    // 80 KB

// scratch
__device__ int    g_newids[4][MTOT];
__device__ int    g_ids32[MTOT];
__device__ __half g_A[(size_t)MTOT * HIDDEN];    // gathered A, fp16 (32 MB)
__device__ __half g_B[(size_t)HIDDEN * HIDDEN];  // packed  B, fp16 (8 MB)

// input_ids arrives either as int32 (harness downcast) or true int64.
// Probe odd 32-bit words of the first 16 elements: all-zero <=> int64 layout.
__global__ void newids_kernel(const unsigned* __restrict__ raw) {
    bool is64 = true;
#pragma unroll
    for (int i = 1; i < 32; i += 2) is64 &= (raw[i] == 0u);

    const long long* as64 = (const long long*)raw;
    const int*       as32 = (const int*)raw;

    int t = blockIdx.x * blockDim.x + threadIdx.x;
    if (t >= MTOT) return;
    int s = t & (SEQ - 1);

    int id0 = is64 ? (int)as64[t] : as32[t];
    int p1v = (s >= 1) ? (is64 ? (int)as64[t - 1] : as32[t - 1]) : EOS_TOK;
    int p2v = (s >= 2) ? (is64 ? (int)as64[t - 2] : as32[t - 2]) : EOS_TOK;

    g_ids32[t] = id0;

    long long sh2 = (s >= 1 && p1v != EOS_TOK) ? p1v : 0;                      // shift-1, EOS-segmented
    long long sh3 = (s >= 2 && p1v != EOS_TOK && p2v != EOS_TOK) ? p2v : 0;    // shift-2, EOS-segmented
#pragma unroll
    for (int e = 0; e < 4; e++) {
        long long dim = HASH_BASE + 2 * e + 1;
        long long m1 = ((long long)VOCAB) % dim;
        long long ng;
        if (e < 2) {
            ng = (long long)id0 + sh2 * m1;              // bigram tables 0,1
        } else {
            long long m2 = (m1 * (long long)VOCAB) % dim;
            ng = (long long)id0 + sh2 * m1 + sh3 * m2;   // trigram tables 2,3
        }
        g_newids[e][t] = (int)(ng % dim);
    }
}

// Gather A rows (emb tables via hashed ids) and pack B rows (projs) to fp16.
__global__ void pack_kernel(const float* __restrict__ e0, const float* __restrict__ e1,
                            const float* __restrict__ e2, const float* __restrict__ e3,
                            const float* __restrict__ p0, const float* __restrict__ p1,
                            const float* __restrict__ p2, const float* __restrict__ p3)
{
    int b = blockIdx.x;
    if (b < MTOT) {
        int t = b;
#pragma unroll
        for (int r = 0; r < 2; r++) {
            int i = threadIdx.x + r * 256;        // float4 index 0..511
            int e = i >> 7;
            int koff = (i & 127) * 4;
            const float* eb = (e == 0) ? e0 : (e == 1) ? e1 : (e == 2) ? e2 : e3;
            int nv = g_newids[e][t];
            float4 v = *reinterpret_cast<const float4*>(eb + (size_t)nv * EMB_DIM + koff);
            __half2 h0 = __floats2half2_rn(v.x, v.y);
            __half2 h1 = __floats2half2_rn(v.z, v.w);
            *reinterpret_cast<__half2*>(g_A + (size_t)t * HIDDEN + e * EMB_DIM + koff)     = h0;
            *reinterpret_cast<__half2*>(g_A + (size_t)t * HIDDEN + e * EMB_DIM + koff + 2) = h1;
        }
    } else {
        int n = b - MTOT;                         // 0..2047
#pragma unroll
        for (int r = 0; r < 2; r++) {
            int i = threadIdx.x + r * 256;
            int e = i >> 7;
            int koff = (i & 127) * 4;
            const float* pb = (e == 0) ? p0 : (e == 1) ? p1 : (e == 2) ? p2 : p3;
            float4 v = *reinterpret_cast<const float4*>(pb + (size_t)n * EMB_DIM + koff);
            __half2 h0 = __floats2half2_rn(v.x, v.y);
            __half2 h1 = __floats2half2_rn(v.z, v.w);
            *reinterpret_cast<__half2*>(g_B + (size_t)n * HIDDEN + e * EMB_DIM + koff)     = h0;
            *reinterpret_cast<__half2*>(g_B + (size_t)n * HIDDEN + e * EMB_DIM + koff + 2) = h1;
        }
    }
}

__device__ __forceinline__ void cp_async16(unsigned dst, const void* src) {
    asm volatile("cp.async.cg.shared.global [%0], [%1], 16;" :: "r"(dst), "l"(src));
}
__device__ __forceinline__ void ldsm_x4(unsigned& r0, unsigned& r1, unsigned& r2, unsigned& r3,
                                        unsigned addr) {
    asm volatile("ldmatrix.sync.aligned.m8n8.x4.shared.b16 {%0,%1,%2,%3}, [%4];"
                 : "=r"(r0), "=r"(r1), "=r"(r2), "=r"(r3) : "r"(addr));
}

__global__ void __launch_bounds__(256, 2)
ngram_gemm_kernel(const float* __restrict__ wemb, float* __restrict__ out)
{
    extern __shared__ char smem[];
    const unsigned smem_u = (unsigned)__cvta_generic_to_shared(smem);
    const int tid  = threadIdx.x;
    const int lane = tid & 31, warp = tid >> 5;
    const int wm = warp >> 2, wn = warp & 3;          // 2 x 4 warp grid (64x32 tiles)
    const int g = lane >> 2, c = lane & 3;
    const int bm = blockIdx.y * BM, bn = blockIdx.x * BN;

    // staging: 512 16B-chunks per tile (128 rows x 4 chunks), 2 per thread
    const int crow = tid >> 1;          // 0..127
    const int cgrp2 = (tid & 1) * 2;    // chunks {0,1} or {2,3}

    // ldmatrix per-lane source rows: phase p = lane>>3 (0..3)
    const int lrow8 = lane & 7;
    const int lphase = lane >> 3;
    // A 16x16 tile: m0=rows0-7/k-lo, m1=rows8-15/k-lo, m2=rows0-7/k-hi, m3=rows8-15/k-hi
    const int a_row_off = (lphase & 1) * 8 + lrow8;       // +8 for m1,m3
    const int a_col_off = (lphase >> 1) * 16;             // +16B for m2,m3
    // B 16x16 tile: m0=rows0-7/k-lo, m1=rows0-7/k-hi, m2=rows8-15/k-lo, m3=rows8-15/k-hi
    const int b_row_off = (lphase >> 1) * 8 + lrow8;
    const int b_col_off = (lphase & 1) * 16;

    float acc[4][4][4];
#pragma unroll
    for (int mf = 0; mf < 4; mf++)
#pragma unroll
        for (int nf = 0; nf < 4; nf++)
#pragma unroll
            for (int r = 0; r < 4; r++) acc[mf][nf][r] = 0.f;

    const __half* Agb = g_A + (size_t)bm * HIDDEN;
    const __half* Bgb = g_B + (size_t)bn * HIDDEN;

    auto issue = [&](int it, int buf) {
        const unsigned sa = smem_u + (unsigned)buf * STAGE_BYTES;
        const unsigned sb = sa + TILE_BYTES;
        const __half* Ag = Agb + it * BK;
        const __half* Bg = Bgb + it * BK;
#pragma unroll
        for (int q = 0; q < 2; q++) {
            int grp = cgrp2 + q;
            cp_async16(sa + crow * ROW_BYTES + grp * 16, Ag + (size_t)crow * HIDDEN + grp * 8);
            cp_async16(sb + crow * ROW_BYTES + grp * 16, Bg + (size_t)crow * HIDDEN + grp * 8);
        }
        asm volatile("cp.async.commit_group;" ::: "memory");
    };

    auto compute = [&](int buf) {
        const unsigned As = smem_u + (unsigned)buf * STAGE_BYTES;
        const unsigned Bs = As + TILE_BYTES;
#pragma unroll
        for (int ks = 0; ks < 2; ks++) {           // two k16 steps cover BK=32
            const int kbyte = ks * 32;
            unsigned av[4][4], bv[4][2];
#pragma unroll
            for (int mf = 0; mf < 4; mf++) {
                const int r0 = wm * 64 + mf * 16;
                ldsm_x4(av[mf][0], av[mf][1], av[mf][2], av[mf][3],
                        As + (unsigned)((r0 + a_row_off) * ROW_BYTES + kbyte + a_col_off));
            }
#pragma unroll
            for (int np = 0; np < 2; np++) {       // nf pairs {0,1},{2,3}
                const int rb = wn * 32 + np * 16;
                ldsm_x4(bv[np * 2][0], bv[np * 2][1], bv[np * 2 + 1][0], bv[np * 2 + 1][1],
                        Bs + (unsigned)((rb + b_row_off) * ROW_BYTES + kbyte + b_col_off));
            }
#pragma unroll
            for (int mf = 0; mf < 4; mf++)
#pragma unroll
                for (int nf = 0; nf < 4; nf++) {
                    asm("mma.sync.aligned.m16n8k16.row.col.f32.f16.f16.f32 "
                        "{%0,%1,%2,%3}, {%4,%5,%6,%7}, {%8,%9}, {%0,%1,%2,%3};"
                        : "+f"(acc[mf][nf][0]), "+f"(acc[mf][nf][1]),
                          "+f"(acc[mf][nf][2]), "+f"(acc[mf][nf][3])
                        : "r"(av[mf][0]), "r"(av[mf][1]), "r"(av[mf][2]), "r"(av[mf][3]),
                          "r"(bv[nf][0]), "r"(bv[nf][1]));
                }
        }
    };

    // 4-stage ring, ONE barrier per iteration over K = 2048 (64 iters of BK=32).
    // After wait+sync for stage 'it', buffer (it+3)%4 == (it-1)%4 was fully
    // consumed by compute(it-1) before this barrier -> safe to refill pre-compute.
    issue(0, 0); issue(1, 1); issue(2, 2);

    for (int it = 0; it < 64; it++) {
        asm volatile("cp.async.wait_group 2;" ::: "memory");
        __syncthreads();                      // stage 'it' visible; compute(it-1) done
        if (it + 3 < 64) issue(it + 3, (it + 3) & 3);
        else asm volatile("cp.async.commit_group;" ::: "memory");  // keep group count uniform
        compute(it & 3);
    }

    // epilogue: fuse word_emb gather + /5 (fp32 accumulators)
    const float inv = 0.2f;
#pragma unroll
    for (int mf = 0; mf < 4; mf++) {
        int r0 = bm + wm * 64 + mf * 16 + g;
        int r1 = r0 + 8;
        int i0 = g_ids32[r0], i1 = g_ids32[r1];
        const float* w0 = wemb + (size_t)i0 * HIDDEN;
        const float* w1 = wemb + (size_t)i1 * HIDDEN;
        float* o0 = out + (size_t)r0 * HIDDEN;
        float* o1 = out + (size_t)r1 * HIDDEN;
#pragma unroll
        for (int nf = 0; nf < 4; nf++) {
            int col = bn + wn * 32 + nf * 8 + 2 * c;
            float2 wa = *reinterpret_cast<const float2*>(w0 + col);
            float2 wb = *reinterpret_cast<const float2*>(w1 + col);
            float2 oa, ob;
            oa.x = (wa.x + acc[mf][nf][0]) * inv;
            oa.y = (wa.y + acc[mf][nf][1]) * inv;
            ob.x = (wb.x + acc[mf][nf][2]) * inv;
            ob.y = (wb.y + acc[mf][nf][3]) * inv;
            *reinterpret_cast<float2*>(o0 + col) = oa;
            *reinterpret_cast<float2*>(o1 + col) = ob;
        }
    }
}

extern "C" void kernel_launch(void* const* d_in, const int* in_sizes, int n_in,
                              void* d_out, int out_size)
{
    const unsigned* ids_raw = (const unsigned*)d_in[0];
    const float*    wemb    = (const float*)d_in[1];
    float* out = (float*)d_out;

    // Bind emb/proj pointers by SIZE (robust to metadata ordering).
    const float* embs[4]  = {nullptr, nullptr, nullptr, nullptr};
    const float* projs[4] = {nullptr, nullptr, nullptr, nullptr};
    int np = 0;
    for (int i = 2; i < n_in && i < 10; i++) {
        long long sz = in_sizes[i];
        if (sz == (long long)HIDDEN * EMB_DIM) {          // 1,048,576 -> proj
            if (np < 4) projs[np++] = (const float*)d_in[i];
        } else {                                           // emb table: unique size per idx
            int dim = (int)(sz / EMB_DIM);
            int idx = (dim - ((int)HASH_BASE + 1)) / 2;
            if (idx >= 0 && idx < 4) embs[idx] = (const float*)d_in[i];
        }
    }

    newids_kernel<<<MTOT / 256, 256>>>(ids_raw);
    pack_kernel<<<MTOT + HIDDEN, 256>>>(embs[0], embs[1], embs[2], embs[3],
                                        projs[0], projs[1], projs[2], projs[3]);

    cudaFuncSetAttribute(ngram_gemm_kernel,
                         cudaFuncAttributeMaxDynamicSharedMemorySize, SMEM_BYTES);
    dim3 grid(HIDDEN / BN, MTOT / BM);  // (16, 64)
    ngram_gemm_kernel<<<grid, 256, SMEM_BYTES>>>(wemb, out);
}